// round 8
// baseline (speedup 1.0000x reference)
#include <cuda_runtime.h>
#include <cuda_bf16.h>
#include <cstdint>
#include <cstddef>

#define BATCH   16384
#define WIDTH   128
#define NNODES  12
#define NEDGES  66
#define NCHUNKS 132                       // sum over v of 2v

#define BM 64
#define THREADS 288                       // 8 consumer warps + 1 producer warp
#define A_TILE_BYTES (64 * 128)           // 64 rows x 64 bf16 = 8 KB
#define W_TILE_BYTES (128 * 128)          // 128 n x 64 bf16 = 16 KB
#define STAGE_BYTES (2 * A_TILE_BYTES + 2 * W_TILE_BYTES)   // 48 KB
#define NSTAGE 2
#define STAGE0_OFF 1024
#define SMEM_TOTAL (STAGE0_OFF + NSTAGE * STAGE_BYTES)      // 99328 B -> 2 CTAs/SM

// mbarrier offsets in smem
#define MB_FULL(s)  ((s) * 8)
#define MB_EMPTY(s) (16 + (s) * 8)

#define OFF_AHI 0
#define OFF_ALO A_TILE_BYTES
#define OFF_WHI (2 * A_TILE_BYTES)
#define OFF_WLO (2 * A_TILE_BYTES + W_TILE_BYTES)

// ---------------- device scratch ----------------
// slot 0 = x (converted); slots 1..10 = node outputs 1..10
__device__ __nv_bfloat16 g_Ahi[11u * BATCH * WIDTH];
__device__ __nv_bfloat16 g_Alo[11u * BATCH * WIDTH];
__device__ __nv_bfloat16 g_Whi[(size_t)NEDGES * WIDTH * WIDTH];  // [e][n][k] transposed
__device__ __nv_bfloat16 g_Wlo[(size_t)NEDGES * WIDTH * WIDTH];

// ---------------- PTX helpers ----------------
__device__ __forceinline__ uint32_t smem_u32(const void* p) {
    uint32_t a;
    asm("{ .reg .u64 t; cvta.to.shared.u64 t, %1; cvt.u32.u64 %0, t; }" : "=r"(a) : "l"(p));
    return a;
}
__device__ __forceinline__ void mbar_init(uint32_t a, uint32_t cnt) {
    asm volatile("mbarrier.init.shared.b64 [%0], %1;" :: "r"(a), "r"(cnt) : "memory");
}
__device__ __forceinline__ void mbar_arrive(uint32_t a) {
    asm volatile("mbarrier.arrive.shared.b64 _, [%0];" :: "r"(a) : "memory");
}
__device__ __forceinline__ void mbar_wait(uint32_t a, uint32_t parity) {
    asm volatile(
        "{\n\t.reg .pred P;\n\t"
        "WL%=:\n\t"
        "mbarrier.try_wait.parity.acquire.cta.shared::cta.b64 P, [%0], %1, 0x989680;\n\t"
        "@!P bra WL%=;\n\t}"
        :: "r"(a), "r"(parity) : "memory");
}
__device__ __forceinline__ void cp_async16(uint32_t dst, const void* src) {
    asm volatile("cp.async.cg.shared.global [%0], [%1], 16;" :: "r"(dst), "l"(src) : "memory");
}
__device__ __forceinline__ void cp_async_arrive_noinc(uint32_t mbar) {
    asm volatile("cp.async.mbarrier.arrive.noinc.shared.b64 [%0];" :: "r"(mbar) : "memory");
}
__device__ __forceinline__ void ldsm4(uint32_t& r0, uint32_t& r1, uint32_t& r2, uint32_t& r3,
                                      uint32_t addr) {
    asm volatile("ldmatrix.sync.aligned.m8n8.x4.shared.b16 {%0,%1,%2,%3}, [%4];"
                 : "=r"(r0), "=r"(r1), "=r"(r2), "=r"(r3) : "r"(addr));
}
__device__ __forceinline__ void mma_bf16(float& d0, float& d1, float& d2, float& d3,
                                         uint32_t a0, uint32_t a1, uint32_t a2, uint32_t a3,
                                         uint32_t b0, uint32_t b1) {
    asm volatile(
        "mma.sync.aligned.m16n8k16.row.col.f32.bf16.bf16.f32 "
        "{%0,%1,%2,%3}, {%4,%5,%6,%7}, {%8,%9}, {%0,%1,%2,%3};"
        : "+f"(d0), "+f"(d1), "+f"(d2), "+f"(d3)
        : "r"(a0), "r"(a1), "r"(a2), "r"(a3), "r"(b0), "r"(b1));
}

// ---------------- W conversion kernel ----------------
__global__ void conv_w_kernel(const float* __restrict__ W) {
    __shared__ float t[32][33];
    const int e  = blockIdx.x;
    const int ti = blockIdx.y;
    const int kt = (ti & 3) * 32;
    const int nt = (ti >> 2) * 32;
    const float* Wb = W + (size_t)e * WIDTH * WIDTH;
#pragma unroll
    for (int r = 0; r < 32; r += 8) {
        int k = kt + threadIdx.y + r;
        t[threadIdx.y + r][threadIdx.x] = Wb[k * WIDTH + nt + threadIdx.x];
    }
    __syncthreads();
    __nv_bfloat16* Hh = g_Whi + (size_t)e * WIDTH * WIDTH;
    __nv_bfloat16* Hl = g_Wlo + (size_t)e * WIDTH * WIDTH;
#pragma unroll
    for (int r = 0; r < 32; r += 8) {
        int n = nt + threadIdx.y + r;
        float v = t[threadIdx.x][threadIdx.y + r];
        __nv_bfloat16 h = __float2bfloat16(v);
        Hh[n * WIDTH + kt + threadIdx.x] = h;
        Hl[n * WIDTH + kt + threadIdx.x] = __float2bfloat16(v - __bfloat162float(h));
    }
}

// chunk cursor: iterates (v, e, kc) over all 132 chunks
struct Cursor {
    int v, e, kc, w;   // w = global edge index = v(v-1)/2 + e
    __device__ __forceinline__ void init() { v = 1; e = 0; kc = 0; w = 0; }
    __device__ __forceinline__ void advance() {
        if (kc == 0) { kc = 1; return; }
        kc = 0; e++; w++;
        if (e == v) { e = 0; v++; w = v * (v - 1) / 2; }
    }
};

// ---------------- fused kernel: all 11 nodes, one launch ----------------
// BM=64 rows/CTA; 8 consumer warps (2x4 grid of 32x32 tiles) + 1 producer; 2 CTAs/SM.
__global__ void __launch_bounds__(THREADS, 2) node_fused_kernel(
    const float* __restrict__ x,
    const float* __restrict__ bias,
    float* __restrict__ out)
{
    extern __shared__ __align__(1024) char smem[];
    const uint32_t sbase = smem_u32(smem);

    const int tid  = threadIdx.x;
    const int lane = tid & 31;
    const int wid  = tid >> 5;
    const int row0 = blockIdx.x * BM;

    if (tid == 0) {
#pragma unroll
        for (int s = 0; s < NSTAGE; s++) {
            mbar_init(sbase + MB_FULL(s), 32);    // producer warp lanes
            mbar_init(sbase + MB_EMPTY(s), 8);    // one per consumer warp
        }
    }

    // ---- inline x conversion for this CTA's 64 rows (row-local) ----
    {
        const float4* xs = (const float4*)(x + (size_t)row0 * WIDTH);
        const size_t ob = (size_t)row0 * WIDTH;
        for (int idx = tid; idx < 2048; idx += THREADS) {
            float4 v = xs[idx];
            __nv_bfloat16 h0 = __float2bfloat16(v.x);
            __nv_bfloat16 h1 = __float2bfloat16(v.y);
            __nv_bfloat16 h2 = __float2bfloat16(v.z);
            __nv_bfloat16 h3 = __float2bfloat16(v.w);
            __nv_bfloat16 l0 = __float2bfloat16(v.x - __bfloat162float(h0));
            __nv_bfloat16 l1 = __float2bfloat16(v.y - __bfloat162float(h1));
            __nv_bfloat16 l2 = __float2bfloat16(v.z - __bfloat162float(h2));
            __nv_bfloat16 l3 = __float2bfloat16(v.w - __bfloat162float(h3));
            uint2 hw = make_uint2(
                (uint32_t)__bfloat16_as_ushort(h0) | ((uint32_t)__bfloat16_as_ushort(h1) << 16),
                (uint32_t)__bfloat16_as_ushort(h2) | ((uint32_t)__bfloat16_as_ushort(h3) << 16));
            uint2 lw = make_uint2(
                (uint32_t)__bfloat16_as_ushort(l0) | ((uint32_t)__bfloat16_as_ushort(l1) << 16),
                (uint32_t)__bfloat16_as_ushort(l2) | ((uint32_t)__bfloat16_as_ushort(l3) << 16));
            *(uint2*)&g_Ahi[ob + (size_t)idx * 4] = hw;
            *(uint2*)&g_Alo[ob + (size_t)idx * 4] = lw;
        }
    }
    __syncthreads();   // mbarrier init + converted x visible to all

    if (wid == 8) {
        // ================= PRODUCER WARP =================
        Cursor pf; pf.init();
        int empty_par[NSTAGE] = {0, 0};
        for (int g = 0; g < NCHUNKS; g++) {
            const int s = g & 1;
            if (g >= NSTAGE) {
                mbar_wait(sbase + MB_EMPTY(s), empty_par[s]);
                empty_par[s] ^= 1;
            }
            const uint32_t stb = sbase + STAGE0_OFF + s * STAGE_BYTES;
            const size_t abase = (size_t)pf.e * (BATCH * WIDTH) + (size_t)row0 * WIDTH + pf.kc * 64;
            const size_t wbase = (size_t)pf.w * (WIDTH * WIDTH) + pf.kc * 64;
            // A: 64 rows x 8 chunks (hi+lo)
#pragma unroll
            for (int j = 0; j < 16; j++) {
                const int idx = j * 32 + lane;       // 0..511
                const int m  = idx >> 3;             // row 0..63
                const int cc = idx & 7;
                const uint32_t sw  = (uint32_t)(m * 128 + ((cc ^ (m & 7)) << 4));
                const size_t  asrc = abase + (size_t)m * WIDTH + cc * 8;
                cp_async16(stb + OFF_AHI + sw, g_Ahi + asrc);
                cp_async16(stb + OFF_ALO + sw, g_Alo + asrc);
            }
            // W: 128 rows x 8 chunks (hi+lo)
#pragma unroll
            for (int j = 0; j < 32; j++) {
                const int idx = j * 32 + lane;       // 0..1023
                const int m  = idx >> 3;             // n row 0..127
                const int cc = idx & 7;
                const uint32_t sw  = (uint32_t)(m * 128 + ((cc ^ (m & 7)) << 4));
                const size_t  wsrc = wbase + (size_t)m * WIDTH + cc * 8;
                cp_async16(stb + OFF_WHI + sw, g_Whi + wsrc);
                cp_async16(stb + OFF_WLO + sw, g_Wlo + wsrc);
            }
            cp_async_arrive_noinc(sbase + MB_FULL(s));
            pf.advance();
        }
        return;
    }

    // ================= CONSUMER WARPS (0..7) =================
    const int warp_moff = (wid & 1) * 32;
    const int warp_noff = (wid >> 1) * 32;

    float acc[2][4][4];
    float sum[2][4][4];
    int full_par[NSTAGE] = {0, 0};

    Cursor cs; cs.init();

    for (int g = 0; g < NCHUNKS; g++) {
        const int s = g & 1;
        mbar_wait(sbase + MB_FULL(s), full_par[s]);
        full_par[s] ^= 1;

        if (cs.kc == 0) {
#pragma unroll
            for (int mi = 0; mi < 2; mi++)
#pragma unroll
                for (int ni = 0; ni < 4; ni++)
#pragma unroll
                    for (int q = 0; q < 4; q++) acc[mi][ni][q] = 0.f;
            if (cs.e == 0) {
#pragma unroll
                for (int mi = 0; mi < 2; mi++)
#pragma unroll
                    for (int ni = 0; ni < 4; ni++)
#pragma unroll
                        for (int q = 0; q < 4; q++) sum[mi][ni][q] = 0.f;
            }
        }

        const uint32_t stb = sbase + STAGE0_OFF + s * STAGE_BYTES;
        const int q4   = lane >> 3;
        const int rsub = lane & 7;

#pragma unroll
        for (int ks = 0; ks < 4; ks++) {
            uint32_t ah[2][4], al[2][4];
            {
                const int arow = warp_moff + (q4 & 1) * 8 + rsub;
                const int ac   = ks * 2 + (q4 >> 1);
#pragma unroll
                for (int mi = 0; mi < 2; mi++) {
                    const int m = arow + mi * 16;
                    const uint32_t off = (uint32_t)(m * 128 + ((ac ^ (m & 7)) << 4));
                    ldsm4(ah[mi][0], ah[mi][1], ah[mi][2], ah[mi][3], stb + OFF_AHI + off);
                    ldsm4(al[mi][0], al[mi][1], al[mi][2], al[mi][3], stb + OFF_ALO + off);
                }
            }
            uint32_t bh[2][4], bl[2][4];
            {
                const int bn0 = warp_noff + (q4 >> 1) * 8 + rsub;
                const int bc  = ks * 2 + (q4 & 1);
#pragma unroll
                for (int np = 0; np < 2; np++) {
                    const int n = bn0 + np * 16;
                    const uint32_t off = (uint32_t)(n * 128 + ((bc ^ (n & 7)) << 4));
                    ldsm4(bh[np][0], bh[np][1], bh[np][2], bh[np][3], stb + OFF_WHI + off);
                    ldsm4(bl[np][0], bl[np][1], bl[np][2], bl[np][3], stb + OFF_WLO + off);
                }
            }
#pragma unroll
            for (int mi = 0; mi < 2; mi++)
#pragma unroll
                for (int ni = 0; ni < 4; ni++) {
                    const int np = ni >> 1, h = (ni & 1) * 2;
                    float* d = acc[mi][ni];
                    mma_bf16(d[0], d[1], d[2], d[3],
                             ah[mi][0], ah[mi][1], ah[mi][2], ah[mi][3],
                             bh[np][h], bh[np][h + 1]);
                    mma_bf16(d[0], d[1], d[2], d[3],
                             ah[mi][0], ah[mi][1], ah[mi][2], ah[mi][3],
                             bl[np][h], bl[np][h + 1]);
                    mma_bf16(d[0], d[1], d[2], d[3],
                             al[mi][0], al[mi][1], al[mi][2], al[mi][3],
                             bh[np][h], bh[np][h + 1]);
                }
        }

        if (cs.kc == 1) {
            // per-edge epilogue: bias + relu + accumulate
            const float* bp = bias + (size_t)cs.w * WIDTH + warp_noff + 2 * (lane & 3);
#pragma unroll
            for (int ni = 0; ni < 4; ni++) {
                const float2 bb = *(const float2*)(bp + ni * 8);
#pragma unroll
                for (int mi = 0; mi < 2; mi++) {
                    sum[mi][ni][0] += fmaxf(acc[mi][ni][0] + bb.x, 0.f);
                    sum[mi][ni][1] += fmaxf(acc[mi][ni][1] + bb.y, 0.f);
                    sum[mi][ni][2] += fmaxf(acc[mi][ni][2] + bb.x, 0.f);
                    sum[mi][ni][3] += fmaxf(acc[mi][ni][3] + bb.y, 0.f);
                }
            }

            if (cs.e == cs.v - 1) {
                // ---- node writeout (before empty-arrive: release ordering) ----
                const int colb = warp_noff + 2 * (lane & 3);
                if (cs.v == NNODES - 1) {
#pragma unroll
                    for (int mi = 0; mi < 2; mi++) {
                        const int r0 = row0 + warp_moff + mi * 16 + (lane >> 2);
#pragma unroll
                        for (int ni = 0; ni < 4; ni++) {
                            const int col = colb + ni * 8;
                            *(float2*)(out + (size_t)r0 * WIDTH + col) =
                                make_float2(sum[mi][ni][0], sum[mi][ni][1]);
                            *(float2*)(out + (size_t)(r0 + 8) * WIDTH + col) =
                                make_float2(sum[mi][ni][2], sum[mi][ni][3]);
                        }
                    }
                } else {
                    const size_t nb = (size_t)cs.v * (BATCH * WIDTH);
#pragma unroll
                    for (int mi = 0; mi < 2; mi++) {
                        const int r0 = row0 + warp_moff + mi * 16 + (lane >> 2);
#pragma unroll
                        for (int ni = 0; ni < 4; ni++) {
                            const int col = colb + ni * 8;
#pragma unroll
                            for (int h = 0; h < 2; h++) {
                                const float s0 = sum[mi][ni][h * 2];
                                const float s1 = sum[mi][ni][h * 2 + 1];
                                const __nv_bfloat16 h0 = __float2bfloat16(s0);
                                const __nv_bfloat16 h1 = __float2bfloat16(s1);
                                const __nv_bfloat16 l0 = __float2bfloat16(s0 - __bfloat162float(h0));
                                const __nv_bfloat16 l1 = __float2bfloat16(s1 - __bfloat162float(h1));
                                const size_t o = nb + (size_t)(r0 + h * 8) * WIDTH + col;
                                *(uint32_t*)&g_Ahi[o] = (uint32_t)__bfloat16_as_ushort(h0) |
                                                        ((uint32_t)__bfloat16_as_ushort(h1) << 16);
                                *(uint32_t*)&g_Alo[o] = (uint32_t)__bfloat16_as_ushort(l0) |
                                                        ((uint32_t)__bfloat16_as_ushort(l1) << 16);
                            }
                        }
                    }
                    __threadfence();   // writeout globally visible before release
                }
            }
        }

        if (lane == 0) mbar_arrive(sbase + MB_EMPTY(s));
        cs.advance();
    }
}

// ---------------- launch ----------------
extern "C" void kernel_launch(void* const* d_in, const int* in_sizes, int n_in,
                              void* d_out, int out_size) {
    const float* x = (const float*)d_in[0];
    const float* W = (const float*)d_in[1];
    const float* b = (const float*)d_in[2];
    float* out = (float*)d_out;

    cudaFuncSetAttribute(node_fused_kernel,
                         cudaFuncAttributeMaxDynamicSharedMemorySize, SMEM_TOTAL);

    conv_w_kernel<<<dim3(NEDGES, 16), dim3(32, 8)>>>(W);
    node_fused_kernel<<<BATCH / BM, THREADS, SMEM_TOTAL>>>(x, b, out);
}

// round 9
// speedup vs baseline: 1.2217x; 1.2217x over previous
#include <cuda_runtime.h>
#include <cstdint>
#include <cstddef>

#define BATCH   16384
#define WIDTH   128
#define NNODES  12
#define NEDGES  66
#define NCHUNKS 132                        // sum over v of 2v (BK=64 chunks)

#define BM 128
#define THREADS 544                        // 16 consumer warps + 1 producer warp
#define TILE_BYTES (128 * 64)              // 128 rows x 64 int8 = 8 KB
#define STAGE_BYTES (4 * TILE_BYTES)       // A1, A0, W1, W0 = 32 KB
#define NSTAGE 3
#define SUM_OFF 1024
#define SUM_BYTES (8 * 512 * 16)           // 64 KB: float4 sumv[8][512]
#define STAGE0_OFF (SUM_OFF + SUM_BYTES)
#define SMEM_TOTAL (STAGE0_OFF + NSTAGE * STAGE_BYTES)   // 164864 B

#define MB_FULL(s)  ((s) * 8)
#define MB_EMPTY(s) (24 + (s) * 8)
#define SA_OFF  64                          // float sA_sm[12]
#define RED_OFF 128                         // float red[17]

#define OFF_A1 0
#define OFF_A0 TILE_BYTES
#define OFF_W1 (2 * TILE_BYTES)
#define OFF_W0 (3 * TILE_BYTES)

// ---------------- device scratch ----------------
// slot 0 = x (quantized); slots 1..10 = node outputs
__device__ int8_t g_A1[11u * BATCH * WIDTH];
__device__ int8_t g_A0[11u * BATCH * WIDTH];
__device__ int8_t g_W1[(size_t)NEDGES * WIDTH * WIDTH];   // [e][n][k] transposed
__device__ int8_t g_W0[(size_t)NEDGES * WIDTH * WIDTH];
__device__ float  g_sWq[NEDGES];     // 16256 / sW
__device__ float  g_sWfold[NEDGES];  // sW / 16256^2

// ---------------- PTX helpers ----------------
__device__ __forceinline__ uint32_t smem_u32(const void* p) {
    uint32_t a;
    asm("{ .reg .u64 t; cvta.to.shared.u64 t, %1; cvt.u32.u64 %0, t; }" : "=r"(a) : "l"(p));
    return a;
}
__device__ __forceinline__ void mbar_init(uint32_t a, uint32_t cnt) {
    asm volatile("mbarrier.init.shared.b64 [%0], %1;" :: "r"(a), "r"(cnt) : "memory");
}
__device__ __forceinline__ void mbar_arrive(uint32_t a) {
    asm volatile("mbarrier.arrive.shared.b64 _, [%0];" :: "r"(a) : "memory");
}
__device__ __forceinline__ void mbar_wait(uint32_t a, uint32_t parity) {
    asm volatile(
        "{\n\t.reg .pred P;\n\t"
        "WL%=:\n\t"
        "mbarrier.try_wait.parity.acquire.cta.shared::cta.b64 P, [%0], %1, 0x989680;\n\t"
        "@!P bra WL%=;\n\t}"
        :: "r"(a), "r"(parity) : "memory");
}
__device__ __forceinline__ void cp_async16(uint32_t dst, const void* src) {
    asm volatile("cp.async.cg.shared.global [%0], [%1], 16;" :: "r"(dst), "l"(src) : "memory");
}
__device__ __forceinline__ void cp_async_arrive_noinc(uint32_t mbar) {
    asm volatile("cp.async.mbarrier.arrive.noinc.shared.b64 [%0];" :: "r"(mbar) : "memory");
}
__device__ __forceinline__ void ldsm4(uint32_t& r0, uint32_t& r1, uint32_t& r2, uint32_t& r3,
                                      uint32_t addr) {
    asm volatile("ldmatrix.sync.aligned.m8n8.x4.shared.b16 {%0,%1,%2,%3}, [%4];"
                 : "=r"(r0), "=r"(r1), "=r"(r2), "=r"(r3) : "r"(addr));
}
__device__ __forceinline__ void mma_s8(int& d0, int& d1, int& d2, int& d3,
                                       uint32_t a0, uint32_t a1, uint32_t a2, uint32_t a3,
                                       uint32_t b0, uint32_t b1) {
    asm volatile(
        "mma.sync.aligned.m16n8k32.row.col.s32.s8.s8.s32 "
        "{%0,%1,%2,%3}, {%4,%5,%6,%7}, {%8,%9}, {%0,%1,%2,%3};"
        : "+r"(d0), "+r"(d1), "+r"(d2), "+r"(d3)
        : "r"(a0), "r"(a1), "r"(a2), "r"(a3), "r"(b0), "r"(b1));
}
__device__ __forceinline__ void bar512() {
    asm volatile("bar.sync 1, 512;" ::: "memory");
}

// swizzled tile address: 128 rows x 64B, 2 rows per 128B line, XOR by line index
__device__ __forceinline__ uint32_t tile_addr(int m, int cc) {
    return (uint32_t)((m >> 1) * 128 + (((((m & 1) << 2) | cc) ^ ((m >> 1) & 7)) << 4));
}

__device__ __forceinline__ void quant2(float h, float inv, int& hi, int& lo) {
    float qf = rintf(h * inv);                 // |qf| <= 16256
    float f1 = rintf(qf * 0.0078125f);         // /128, |f1| <= 127
    hi = (int)f1;
    lo = (int)(qf - 128.0f * f1);              // in [-64, 64]
}

// ---------------- W preprocessing ----------------
__global__ void w_max_kernel(const float* __restrict__ W) {
    __shared__ float red[8];
    const int e = blockIdx.x;
    const float* Wb = W + (size_t)e * WIDTH * WIDTH;
    float mx = 0.f;
    for (int i = threadIdx.x; i < WIDTH * WIDTH; i += 256) mx = fmaxf(mx, fabsf(Wb[i]));
    for (int o = 16; o; o >>= 1) mx = fmaxf(mx, __shfl_xor_sync(0xffffffffu, mx, o));
    if ((threadIdx.x & 31) == 0) red[threadIdx.x >> 5] = mx;
    __syncthreads();
    if (threadIdx.x == 0) {
#pragma unroll
        for (int i = 1; i < 8; i++) mx = fmaxf(mx, red[i]);
        mx = fmaxf(mx, 1e-30f);
        g_sWq[e]    = 16256.0f / mx;
        g_sWfold[e] = mx / (16256.0f * 16256.0f);
    }
}

// W[e][k][n] fp32 -> g_W{1,0}[e][n][k] int8 (transpose + fixed-point split)
__global__ void w_quant_kernel(const float* __restrict__ W) {
    __shared__ float t[32][33];
    const int e  = blockIdx.x;
    const int ti = blockIdx.y;
    const int kt = (ti & 3) * 32;
    const int nt = (ti >> 2) * 32;
    const float qs = g_sWq[e];
    const float* Wb = W + (size_t)e * WIDTH * WIDTH;
#pragma unroll
    for (int r = 0; r < 32; r += 8) {
        int k = kt + threadIdx.y + r;
        t[threadIdx.y + r][threadIdx.x] = Wb[k * WIDTH + nt + threadIdx.x];
    }
    __syncthreads();
    int8_t* H1 = g_W1 + (size_t)e * WIDTH * WIDTH;
    int8_t* H0 = g_W0 + (size_t)e * WIDTH * WIDTH;
#pragma unroll
    for (int r = 0; r < 32; r += 8) {
        int n = nt + threadIdx.y + r;
        float v = t[threadIdx.x][threadIdx.y + r];
        int hi, lo;
        quant2(v, qs, hi, lo);
        H1[n * WIDTH + kt + threadIdx.x] = (int8_t)hi;
        H0[n * WIDTH + kt + threadIdx.x] = (int8_t)lo;
    }
}

// chunk cursor
struct Cursor {
    int v, e, kc, w;
    __device__ __forceinline__ void init() { v = 1; e = 0; kc = 0; w = 0; }
    __device__ __forceinline__ void advance() {
        if (kc == 0) { kc = 1; return; }
        kc = 0; e++; w++;
        if (e == v) { e = 0; v++; w = v * (v - 1) / 2; }
    }
};

// ---------------- fused kernel ----------------
__global__ void __launch_bounds__(THREADS, 1) node_fused_kernel(
    const float* __restrict__ x,
    const float* __restrict__ bias,
    float* __restrict__ out)
{
    extern __shared__ __align__(1024) char smem[];
    const uint32_t sbase = smem_u32(smem);
    float*  sA_sm = (float*)(smem + SA_OFF);
    float*  red   = (float*)(smem + RED_OFF);
    float4* sumv  = (float4*)(smem + SUM_OFF);

    const int tid  = threadIdx.x;
    const int lane = tid & 31;
    const int wid  = tid >> 5;
    const int row0 = blockIdx.x * BM;

    if (tid == 0) {
#pragma unroll
        for (int s = 0; s < NSTAGE; s++) {
            mbar_init(sbase + MB_FULL(s), 32);
            mbar_init(sbase + MB_EMPTY(s), 16);
        }
    }

    // ---- x quantization for this CTA's 128 rows ----
    {
        const float4* xs = (const float4*)(x + (size_t)row0 * WIDTH);
        float mx = 0.f;
        for (int i = tid; i < 4096; i += THREADS) {
            float4 v = xs[i];
            mx = fmaxf(mx, fmaxf(fmaxf(fabsf(v.x), fabsf(v.y)), fmaxf(fabsf(v.z), fabsf(v.w))));
        }
        for (int o = 16; o; o >>= 1) mx = fmaxf(mx, __shfl_xor_sync(0xffffffffu, mx, o));
        if (lane == 0) red[wid] = mx;
        __syncthreads();
        mx = red[0];
#pragma unroll
        for (int i = 1; i < 17; i++) mx = fmaxf(mx, red[i]);
        const float sA = fmaxf(mx, 1e-30f);
        if (tid == 0) sA_sm[0] = sA;
        const float inv = 16256.0f / sA;
        for (int i = tid; i < 4096; i += THREADS) {
            float4 v = xs[i];
            int h0, l0, h1, l1, h2, l2, h3, l3;
            quant2(v.x, inv, h0, l0); quant2(v.y, inv, h1, l1);
            quant2(v.z, inv, h2, l2); quant2(v.w, inv, h3, l3);
            char4 c1 = make_char4((char)h0, (char)h1, (char)h2, (char)h3);
            char4 c0 = make_char4((char)l0, (char)l1, (char)l2, (char)l3);
            *(char4*)(g_A1 + (size_t)row0 * WIDTH + (size_t)i * 4) = c1;
            *(char4*)(g_A0 + (size_t)row0 * WIDTH + (size_t)i * 4) = c0;
        }
    }
    __syncthreads();   // x data + barriers + sA_sm[0] visible

    if (wid == 16) {
        // ================= PRODUCER WARP =================
        Cursor pf; pf.init();
        int empty_par[NSTAGE] = {0, 0, 0};
        for (int g = 0; g < NCHUNKS; g++) {
            const int s = g % NSTAGE;
            if (g >= NSTAGE) {
                mbar_wait(sbase + MB_EMPTY(s), empty_par[s]);
                empty_par[s] ^= 1;
            }
            const uint32_t stb = sbase + STAGE0_OFF + s * STAGE_BYTES;
            const size_t abase = (size_t)pf.e * (BATCH * WIDTH) + (size_t)row0 * WIDTH + pf.kc * 64;
            const size_t wbase = (size_t)pf.w * (WIDTH * WIDTH) + pf.kc * 64;
#pragma unroll
            for (int j = 0; j < 16; j++) {
                const int idx = j * 32 + lane;     // 0..511
                const int m  = idx >> 2;           // row 0..127
                const int cc = idx & 3;            // 16B chunk in 64B row
                const uint32_t sw = tile_addr(m, cc);
                const size_t asrc = abase + (size_t)m * WIDTH + cc * 16;
                const size_t wsrc = wbase + (size_t)m * WIDTH + cc * 16;
                cp_async16(stb + OFF_A1 + sw, g_A1 + asrc);
                cp_async16(stb + OFF_A0 + sw, g_A0 + asrc);
                cp_async16(stb + OFF_W1 + sw, g_W1 + wsrc);
                cp_async16(stb + OFF_W0 + sw, g_W0 + wsrc);
            }
            cp_async_arrive_noinc(sbase + MB_FULL(s));
            pf.advance();
        }
        return;
    }

    // ================= CONSUMER WARPS (0..15) =================
    const int warp_moff = (wid & 3) * 32;
    const int warp_noff = (wid >> 2) * 32;

    int p11[2][4][4];
    int pm [2][4][4];
    int full_par[NSTAGE] = {0, 0, 0};

    Cursor cs; cs.init();

    for (int g = 0; g < NCHUNKS; g++) {
        const int s = g % NSTAGE;
        mbar_wait(sbase + MB_FULL(s), full_par[s]);
        full_par[s] ^= 1;

        if (cs.kc == 0) {
#pragma unroll
            for (int mi = 0; mi < 2; mi++)
#pragma unroll
                for (int ni = 0; ni < 4; ni++)
#pragma unroll
                    for (int q = 0; q < 4; q++) { p11[mi][ni][q] = 0; pm[mi][ni][q] = 0; }
        }

        const uint32_t stb = sbase + STAGE0_OFF + s * STAGE_BYTES;
        const int q4   = lane >> 3;
        const int rsub = lane & 7;

#pragma unroll
        for (int ks = 0; ks < 2; ks++) {
            const int arow = warp_moff + (q4 & 1) * 8 + rsub;
            const int acc_c = ks * 2 + (q4 >> 1);
            const int bn   = warp_noff + (q4 >> 1) * 8 + rsub;
            const int bcc  = ks * 2 + (q4 & 1);

            uint32_t a1f[2][4], b1f[2][4];
#pragma unroll
            for (int mi = 0; mi < 2; mi++)
                ldsm4(a1f[mi][0], a1f[mi][1], a1f[mi][2], a1f[mi][3],
                      stb + OFF_A1 + tile_addr(arow + mi * 16, acc_c));
#pragma unroll
            for (int np = 0; np < 2; np++)
                ldsm4(b1f[np][0], b1f[np][1], b1f[np][2], b1f[np][3],
                      stb + OFF_W1 + tile_addr(bn + np * 16, bcc));
            // P11 += a1*b1
#pragma unroll
            for (int mi = 0; mi < 2; mi++)
#pragma unroll
                for (int ni = 0; ni < 4; ni++) {
                    const int np = ni >> 1, h = (ni & 1) * 2;
                    mma_s8(p11[mi][ni][0], p11[mi][ni][1], p11[mi][ni][2], p11[mi][ni][3],
                           a1f[mi][0], a1f[mi][1], a1f[mi][2], a1f[mi][3],
                           b1f[np][h], b1f[np][h + 1]);
                }
            // Pmid += a0*b1
            uint32_t a0f[2][4];
#pragma unroll
            for (int mi = 0; mi < 2; mi++)
                ldsm4(a0f[mi][0], a0f[mi][1], a0f[mi][2], a0f[mi][3],
                      stb + OFF_A0 + tile_addr(arow + mi * 16, acc_c));
#pragma unroll
            for (int mi = 0; mi < 2; mi++)
#pragma unroll
                for (int ni = 0; ni < 4; ni++) {
                    const int np = ni >> 1, h = (ni & 1) * 2;
                    mma_s8(pm[mi][ni][0], pm[mi][ni][1], pm[mi][ni][2], pm[mi][ni][3],
                           a0f[mi][0], a0f[mi][1], a0f[mi][2], a0f[mi][3],
                           b1f[np][h], b1f[np][h + 1]);
                }
            // Pmid += a1*b0
            uint32_t b0f[2][4];
#pragma unroll
            for (int np = 0; np < 2; np++)
                ldsm4(b0f[np][0], b0f[np][1], b0f[np][2], b0f[np][3],
                      stb + OFF_W0 + tile_addr(bn + np * 16, bcc));
#pragma unroll
            for (int mi = 0; mi < 2; mi++)
#pragma unroll
                for (int ni = 0; ni < 4; ni++) {
                    const int np = ni >> 1, h = (ni & 1) * 2;
                    mma_s8(pm[mi][ni][0], pm[mi][ni][1], pm[mi][ni][2], pm[mi][ni][3],
                           a1f[mi][0], a1f[mi][1], a1f[mi][2], a1f[mi][3],
                           b0f[np][h], b0f[np][h + 1]);
                }
        }

        if (cs.kc == 1) {
            // ---- per-edge fold: dequant + bias + relu + accumulate in smem ----
            const float sc = sA_sm[cs.e] * g_sWfold[cs.w];
            const float* bp = bias + (size_t)cs.w * WIDTH + warp_noff + 2 * (lane & 3);
            const bool last  = (cs.e == cs.v - 1);
            const bool final_node = (cs.v == NNODES - 1);
            float mxloc = 0.f;
#pragma unroll
            for (int mi = 0; mi < 2; mi++)
#pragma unroll
                for (int ni = 0; ni < 4; ni++) {
                    const int i4 = mi * 4 + ni;
                    float4 sv;
                    if (cs.e == 0) sv = make_float4(0.f, 0.f, 0.f, 0.f);
                    else           sv = sumv[i4 * 512 + tid];
                    const float2 bb = *(const float2*)(bp + ni * 8);
                    float v0 = fmaf(16384.f, (float)p11[mi][ni][0], 128.f * (float)pm[mi][ni][0]) * sc + bb.x;
                    float v1 = fmaf(16384.f, (float)p11[mi][ni][1], 128.f * (float)pm[mi][ni][1]) * sc + bb.y;
                    float v2 = fmaf(16384.f, (float)p11[mi][ni][2], 128.f * (float)pm[mi][ni][2]) * sc + bb.x;
                    float v3 = fmaf(16384.f, (float)p11[mi][ni][3], 128.f * (float)pm[mi][ni][3]) * sc + bb.y;
                    sv.x += fmaxf(v0, 0.f);
                    sv.y += fmaxf(v1, 0.f);
                    sv.z += fmaxf(v2, 0.f);
                    sv.w += fmaxf(v3, 0.f);
                    if (last && final_node) {
                        const int col = warp_noff + 2 * (lane & 3) + ni * 8;
                        const int r0  = row0 + warp_moff + mi * 16 + (lane >> 2);
                        *(float2*)(out + (size_t)r0 * WIDTH + col)       = make_float2(sv.x, sv.y);
                        *(float2*)(out + (size_t)(r0 + 8) * WIDTH + col) = make_float2(sv.z, sv.w);
                    } else {
                        sumv[i4 * 512 + tid] = sv;
                        if (last) {
                            mxloc = fmaxf(mxloc, fmaxf(fmaxf(fabsf(sv.x), fabsf(sv.y)),
                                                       fmaxf(fabsf(sv.z), fabsf(sv.w))));
                        }
                    }
                }

            if (last && !final_node) {
                // ---- node end: block max -> quantize -> store int8 ----
                for (int o = 16; o; o >>= 1) mxloc = fmaxf(mxloc, __shfl_xor_sync(0xffffffffu, mxloc, o));
                if (lane == 0) red[wid] = mxloc;
                bar512();
                float mx = red[0];
#pragma unroll
                for (int i = 1; i < 16; i++) mx = fmaxf(mx, red[i]);
                const float sA = fmaxf(mx, 1e-30f);
                if (tid == 0) sA_sm[cs.v] = sA;
                bar512();   // sA_sm[v] visible before any later-edge read
                const float inv = 16256.0f / sA;
                const size_t vb = (size_t)cs.v * (BATCH * WIDTH);
#pragma unroll
                for (int mi = 0; mi < 2; mi++)
#pragma unroll
                    for (int ni = 0; ni < 4; ni++) {
                        const float4 sv = sumv[(mi * 4 + ni) * 512 + tid];
                        const int col = warp_noff + 2 * (lane & 3) + ni * 8;
                        const int r0  = row0 + warp_moff + mi * 16 + (lane >> 2);
                        int h0, l0, h1, l1, h2, l2, h3, l3;
                        quant2(sv.x, inv, h0, l0); quant2(sv.y, inv, h1, l1);
                        quant2(sv.z, inv, h2, l2); quant2(sv.w, inv, h3, l3);
                        *(char2*)(g_A1 + vb + (size_t)r0 * WIDTH + col)       = make_char2((char)h0, (char)h1);
                        *(char2*)(g_A0 + vb + (size_t)r0 * WIDTH + col)       = make_char2((char)l0, (char)l1);
                        *(char2*)(g_A1 + vb + (size_t)(r0 + 8) * WIDTH + col) = make_char2((char)h2, (char)h3);
                        *(char2*)(g_A0 + vb + (size_t)(r0 + 8) * WIDTH + col) = make_char2((char)l2, (char)l3);
                    }
                __threadfence();
            }
        }

        if (lane == 0) mbar_arrive(sbase + MB_EMPTY(s));
        cs.advance();
    }
}

// ---------------- launch ----------------
extern "C" void kernel_launch(void* const* d_in, const int* in_sizes, int n_in,
                              void* d_out, int out_size) {
    const float* x = (const float*)d_in[0];
    const float* W = (const float*)d_in[1];
    const float* b = (const float*)d_in[2];
    float* out = (float*)d_out;

    cudaFuncSetAttribute(node_fused_kernel,
                         cudaFuncAttributeMaxDynamicSharedMemorySize, SMEM_TOTAL);

    w_max_kernel<<<NEDGES, 256>>>(W);
    w_quant_kernel<<<dim3(NEDGES, 16), dim3(32, 8)>>>(W);
    node_fused_kernel<<<BATCH / BM, THREADS, SMEM_TOTAL>>>(x, b, out);
}